// round 4
// baseline (speedup 1.0000x reference)
#include <cuda_runtime.h>
#include <cuda_bf16.h>
#include <cfloat>
#include <cstdint>

// Problem constants
#define B_   65536
#define I_   640     // input dim (K of encode GEMM)
#define L_   2560    // latent dim
#define K_   32      // top-k
#define C_   40      // candidates per row (approx top-C, rescored exactly)

// Encode tiling: block = 64 rows x 128 cols, 8 warps, warp tile 32x32
#define BM   64
#define BN   128
#define NTHR 256

// ---------------------------------------------------------------------------
// Device-global scratch (no allocation allowed)
// ---------------------------------------------------------------------------
__device__ float          g_WdT[(size_t)L_ * I_];   // transposed decoder
__device__ __nv_bfloat16  g_wb[(size_t)L_ * I_];    // We in bf16
__device__ short          g_cand[(size_t)B_ * C_];  // candidate col indices

// ---------------------------------------------------------------------------
// SMEM layout for encode kernel (byte offsets)
//   A: [20 chunks][64 rows][40 halves]  (80B row pitch -> conflict-free ldmatrix)
//   B: [2 bufs][128 n][40 halves]
//   Cs: transposed [128 n][65 floats]   (stride 65 -> conflict-free scan)
// ---------------------------------------------------------------------------
#define SM_A    0
#define SM_B    102400
#define SM_CS   122880
#define SM_SV   156160
#define SM_SI   166656
#define SM_BE   171904
#define SM_TOT  172416

__device__ __forceinline__ uint32_t smem_u32(const void* p) {
    uint32_t a;
    asm("{ .reg .u64 t; cvta.to.shared.u64 t, %1; cvt.u32.u64 %0, t; }"
        : "=r"(a) : "l"(p));
    return a;
}

__device__ __forceinline__ void ldmatrix_x4(uint32_t& a0, uint32_t& a1,
                                            uint32_t& a2, uint32_t& a3,
                                            uint32_t addr) {
    asm volatile("ldmatrix.sync.aligned.m8n8.x4.shared.b16 {%0,%1,%2,%3}, [%4];"
                 : "=r"(a0), "=r"(a1), "=r"(a2), "=r"(a3) : "r"(addr));
}

__device__ __forceinline__ void mma16816(float& c0, float& c1, float& c2, float& c3,
                                         uint32_t a0, uint32_t a1, uint32_t a2,
                                         uint32_t a3, uint32_t b0, uint32_t b1) {
    asm volatile(
        "mma.sync.aligned.m16n8k16.row.col.f32.bf16.bf16.f32 "
        "{%0,%1,%2,%3}, {%4,%5,%6,%7}, {%8,%9}, {%0,%1,%2,%3};"
        : "+f"(c0), "+f"(c1), "+f"(c2), "+f"(c3)
        : "r"(a0), "r"(a1), "r"(a2), "r"(a3), "r"(b0), "r"(b1));
}

__device__ __forceinline__ uint32_t lds32(uint32_t addr) {
    uint32_t v;
    asm volatile("ld.shared.b32 %0, [%1];" : "=r"(v) : "r"(addr));
    return v;
}

// ---------------------------------------------------------------------------
// Kernel: transpose Wd [I_, L_] -> WdT [L_, I_]
// ---------------------------------------------------------------------------
__global__ void transpose_wd_kernel(const float* __restrict__ Wd) {
    __shared__ float tile[32][33];
    const int l0 = blockIdx.x * 32, i0 = blockIdx.y * 32;
    const int tx = threadIdx.x, ty = threadIdx.y;
    #pragma unroll
    for (int r = ty; r < 32; r += 8)
        tile[r][tx] = Wd[(size_t)(i0 + r) * L_ + l0 + tx];
    __syncthreads();
    #pragma unroll
    for (int r = ty; r < 32; r += 8)
        g_WdT[(size_t)(l0 + r) * I_ + i0 + tx] = tile[tx][r];
}

// ---------------------------------------------------------------------------
// Kernel: convert We fp32 -> bf16
// ---------------------------------------------------------------------------
__global__ void convert_we_kernel(const float* __restrict__ We) {
    size_t i = ((size_t)blockIdx.x * blockDim.x + threadIdx.x) * 8;
    if (i >= (size_t)L_ * I_) return;
    float4 f0 = *(const float4*)(We + i);
    float4 f1 = *(const float4*)(We + i + 4);
    __nv_bfloat162 h0 = __floats2bfloat162_rn(f0.x, f0.y);
    __nv_bfloat162 h1 = __floats2bfloat162_rn(f0.z, f0.w);
    __nv_bfloat162 h2 = __floats2bfloat162_rn(f1.x, f1.y);
    __nv_bfloat162 h3 = __floats2bfloat162_rn(f1.z, f1.w);
    uint4 pk = make_uint4(*(uint32_t*)&h0, *(uint32_t*)&h1,
                          *(uint32_t*)&h2, *(uint32_t*)&h3);
    *(uint4*)(g_wb + i) = pk;
}

// ---------------------------------------------------------------------------
// Kernel: bf16 mma.sync encode GEMM + fused approx top-C + zero-fill
//   grid = B_/BM = 1024, 256 threads, 1 CTA/SM
// ---------------------------------------------------------------------------
__global__ void __launch_bounds__(NTHR, 1)
encode_topk_kernel(const float* __restrict__ x,
                   const float* __restrict__ be,
                   float* __restrict__ sparse_out) {
    extern __shared__ __align__(128) char smem[];
    const uint32_t sb = smem_u32(smem);
    float* Cs  = (float*)(smem + SM_CS);
    float* sv  = (float*)(smem + SM_SV);
    short* si  = (short*)(smem + SM_SI);
    float* sbe = (float*)(smem + SM_BE);

    const int tid  = threadIdx.x;
    const int warp = tid >> 5;
    const int lane = tid & 31;
    const int g    = lane >> 2;     // mma group id
    const int tg   = lane & 3;      // mma thread-in-group
    const int warp_m = warp & 1;    // 2 m-groups of 32 rows
    const int warp_n = warp >> 1;   // 4 n-groups of 32 cols
    const int row0 = blockIdx.x * BM;

    // init candidate lists
    for (int i = tid; i < BM * C_; i += NTHR) {
        int r = i / C_, k = i % C_;
        sv[r * 41 + k] = -FLT_MAX;
        si[r * 41 + k] = 32767;
    }

    // Stage full A: x[row0..+64][0..640] fp32 -> bf16, chunked [20][64][40h]
    #pragma unroll 4
    for (int it = 0; it < 40; ++it) {
        int u  = tid + it * NTHR;       // < 10240
        int m  = u / 160;
        int k4 = u % 160;
        float4 f = *(const float4*)(x + (size_t)(row0 + m) * I_ + k4 * 4);
        __nv_bfloat162 h0 = __floats2bfloat162_rn(f.x, f.y);
        __nv_bfloat162 h1 = __floats2bfloat162_rn(f.z, f.w);
        uint2 pk = make_uint2(*(uint32_t*)&h0, *(uint32_t*)&h1);
        int chunk = k4 >> 3, kin = (k4 & 7) * 4;
        *(uint2*)(smem + SM_A + chunk * 5120 + m * 80 + kin * 2) = pk;
    }
    __syncthreads();

    // ldmatrix lane offset (within A chunk): row = warp_m*32 + (lane&15), colgrp = lane>>4
    const uint32_t a_lane_off =
        (uint32_t)((warp_m * 32 + (lane & 15)) * 80 + (lane >> 4) * 16);
    // B fragment lane offset (within B buf): n = warp_n*32 + g, k byte = tg*4
    const uint32_t b_lane_off = (uint32_t)((warp_n * 32 + g) * 80 + tg * 4);

    float minv = -FLT_MAX;
    int   mini = 32767;

    for (int ct = 0; ct < L_ / BN; ++ct) {
        const int col0 = ct * BN;

        float acc[2][4][4];
        #pragma unroll
        for (int mt = 0; mt < 2; ++mt)
            #pragma unroll
            for (int nt = 0; nt < 4; ++nt)
                #pragma unroll
                for (int r = 0; r < 4; ++r) acc[mt][nt][r] = 0.f;

        // preload B chunk 0
        {
            #pragma unroll
            for (int it = 0; it < 2; ++it) {
                int u = tid + it * NTHR;         // < 512
                int n = u >> 2, q = u & 3;
                uint4 v = *(const uint4*)(g_wb + (size_t)(col0 + n) * I_ + q * 8);
                *(uint4*)(smem + SM_B + n * 80 + q * 16) = v;
            }
        }
        __syncthreads();

        for (int chunk = 0; chunk < 20; ++chunk) {
            const int buf = chunk & 1;
            uint4 pf0, pf1;
            const bool pf = (chunk < 19);
            if (pf) {
                int u0 = tid, u1 = tid + NTHR;
                int n0 = u0 >> 2, q0 = u0 & 3;
                int n1 = u1 >> 2, q1 = u1 & 3;
                const __nv_bfloat16* src = g_wb + (size_t)col0 * I_ + (chunk + 1) * 32;
                pf0 = *(const uint4*)(src + (size_t)n0 * I_ + q0 * 8);
                pf1 = *(const uint4*)(src + (size_t)n1 * I_ + q1 * 8);
            }

            const uint32_t a_chunk = sb + SM_A + chunk * 5120 + a_lane_off;
            const uint32_t b_buf   = sb + SM_B + buf * 10240 + b_lane_off;

            #pragma unroll
            for (int k16 = 0; k16 < 2; ++k16) {
                uint32_t a[2][4];
                #pragma unroll
                for (int mt = 0; mt < 2; ++mt)
                    ldmatrix_x4(a[mt][0], a[mt][1], a[mt][2], a[mt][3],
                                a_chunk + mt * 16 * 80 + k16 * 32);
                uint32_t b0[4], b1[4];
                #pragma unroll
                for (int nt = 0; nt < 4; ++nt) {
                    uint32_t ba = b_buf + nt * 640 + k16 * 32;
                    b0[nt] = lds32(ba);
                    b1[nt] = lds32(ba + 16);
                }
                #pragma unroll
                for (int mt = 0; mt < 2; ++mt)
                    #pragma unroll
                    for (int nt = 0; nt < 4; ++nt)
                        mma16816(acc[mt][nt][0], acc[mt][nt][1],
                                 acc[mt][nt][2], acc[mt][nt][3],
                                 a[mt][0], a[mt][1], a[mt][2], a[mt][3],
                                 b0[nt], b1[nt]);
            }

            if (pf) {
                char* dst = smem + SM_B + (buf ^ 1) * 10240;
                int u0 = tid, u1 = tid + NTHR;
                *(uint4*)(dst + (u0 >> 2) * 80 + (u0 & 3) * 16) = pf0;
                *(uint4*)(dst + (u1 >> 2) * 80 + (u1 & 3) * 16) = pf1;
            }
            __syncthreads();
        }

        // dump accumulators to transposed Cs[n][m] (stride 65)
        #pragma unroll
        for (int mt = 0; mt < 2; ++mt) {
            int row = warp_m * 32 + mt * 16 + g;
            #pragma unroll
            for (int nt = 0; nt < 4; ++nt) {
                int col = warp_n * 32 + nt * 8 + tg * 2;
                Cs[col * 65 + row]           = acc[mt][nt][0];
                Cs[(col + 1) * 65 + row]     = acc[mt][nt][1];
                Cs[col * 65 + row + 8]       = acc[mt][nt][2];
                Cs[(col + 1) * 65 + row + 8] = acc[mt][nt][3];
            }
        }
        if (tid >= 128) sbe[tid - 128] = be[col0 + tid - 128];
        __syncthreads();

        // streaming top-C update: thread t owns row t (conflict-free scan)
        if (tid < BM) {
            const int lbase = tid * 41;
            #pragma unroll 1
            for (int n = 0; n < BN; ++n) {
                float v = Cs[n * 65 + tid] + sbe[n];
                int col = col0 + n;
                if (v > minv || (v == minv && col < mini)) {
                    int p = C_ - 1;
                    while (p > 0) {
                        float pv = sv[lbase + p - 1];
                        int   pi = si[lbase + p - 1];
                        if (v > pv || (v == pv && col < pi)) {
                            sv[lbase + p] = pv; si[lbase + p] = (short)pi; --p;
                        } else break;
                    }
                    sv[lbase + p] = v; si[lbase + p] = (short)col;
                    minv = sv[lbase + C_ - 1];
                    mini = si[lbase + C_ - 1];
                }
            }
        }
        __syncthreads();
    }

    // publish candidate indices
    if (tid < BM) {
        #pragma unroll
        for (int k = 0; k < C_; ++k)
            g_cand[(size_t)(row0 + tid) * C_ + k] = si[tid * 41 + k];
    }

    // zero-fill this block's sparse region
    float4 z = make_float4(0.f, 0.f, 0.f, 0.f);
    float4* sp = (float4*)(sparse_out + (size_t)row0 * L_);
    for (int i = tid; i < BM * L_ / 4; i += NTHR) sp[i] = z;
}

// ---------------------------------------------------------------------------
// Kernel: exact fp32 rescore of C_ candidates + exact top-32 select
//         + sparse scatter + fused decode.  One block per row, 128 threads.
// ---------------------------------------------------------------------------
__global__ void __launch_bounds__(128)
rescore_decode_kernel(const float* __restrict__ x,
                      const float* __restrict__ We,
                      const float* __restrict__ be,
                      const float* __restrict__ bd,
                      float* __restrict__ sparse_out,
                      float* __restrict__ recon) {
    __shared__ float sx[I_];
    __shared__ float cv[C_];
    __shared__ int   ci[C_];
    __shared__ float sv2[K_];
    __shared__ int   si2[K_];
    const int b = blockIdx.x, t = threadIdx.x;
    const int wp = t >> 5, ln = t & 31;

    const float4* xr = (const float4*)(x + (size_t)b * I_);
    for (int i = t; i < I_ / 4; i += 128) ((float4*)sx)[i] = xr[i];
    if (t < C_) ci[t] = (int)g_cand[(size_t)b * C_ + t];
    __syncthreads();

    // exact fp32 dot for each candidate (warp per 10 candidates)
    #pragma unroll 1
    for (int j = 0; j < C_ / 4; ++j) {
        const int c   = wp * (C_ / 4) + j;
        const int col = ci[c];
        const float4* w = (const float4*)(We + (size_t)col * I_);
        float acc = 0.f;
        #pragma unroll
        for (int q = 0; q < I_ / 128; ++q) {
            float4 a = ((const float4*)sx)[ln + q * 32];
            float4 v = __ldg(&w[ln + q * 32]);
            acc = fmaf(a.x, v.x, acc); acc = fmaf(a.y, v.y, acc);
            acc = fmaf(a.z, v.z, acc); acc = fmaf(a.w, v.w, acc);
        }
        #pragma unroll
        for (int s = 16; s; s >>= 1) acc += __shfl_xor_sync(0xffffffffu, acc, s);
        if (ln == 0) cv[c] = acc + __ldg(&be[col]);
    }
    __syncthreads();

    // exact rank (val desc, idx asc — jax tie rules); winners scatter
    if (t < C_) {
        const float v  = cv[t];
        const int   id = ci[t];
        int rank = 0;
        #pragma unroll
        for (int c = 0; c < C_; ++c) {
            if (c == t) continue;
            float vc = cv[c]; int ic = ci[c];
            rank += (vc > v) || (vc == v && ic < id);
        }
        if (rank < K_) {
            sparse_out[(size_t)b * L_ + id] = v;
            sv2[rank] = v;
            si2[rank] = id;
        }
    }
    __syncthreads();

    // fused decode: recon[b,i] = bd[i] + sum_k v_k * WdT[idx_k, i]
    float acc[5];
    #pragma unroll
    for (int j = 0; j < 5; ++j) acc[j] = __ldg(&bd[t + j * 128]);
    #pragma unroll 1
    for (int k = 0; k < K_; ++k) {
        float v = sv2[k];
        const float* cw = g_WdT + (size_t)si2[k] * I_;
        #pragma unroll
        for (int j = 0; j < 5; ++j)
            acc[j] = fmaf(v, __ldg(&cw[t + j * 128]), acc[j]);
    }
    #pragma unroll
    for (int j = 0; j < 5; ++j)
        recon[(size_t)b * I_ + t + j * 128] = acc[j];
}

// ---------------------------------------------------------------------------
// Launch
// ---------------------------------------------------------------------------
extern "C" void kernel_launch(void* const* d_in, const int* in_sizes, int n_in,
                              void* d_out, int out_size) {
    const float* x  = (const float*)d_in[0];   // [65536, 640]
    const float* We = (const float*)d_in[1];   // [2560, 640]
    const float* be = (const float*)d_in[2];   // [2560]
    const float* Wd = (const float*)d_in[3];   // [640, 2560]
    const float* bd = (const float*)d_in[4];   // [640]

    float* recon  = (float*)d_out;                    // [B_, I_]
    float* sparse = (float*)d_out + (size_t)B_ * I_;  // [B_, L_]

    cudaFuncSetAttribute(encode_topk_kernel,
                         cudaFuncAttributeMaxDynamicSharedMemorySize, SM_TOT);

    transpose_wd_kernel<<<dim3(L_ / 32, I_ / 32), dim3(32, 8)>>>(Wd);
    convert_we_kernel<<<(L_ * I_ / 8 + 255) / 256, 256>>>(We);
    encode_topk_kernel<<<B_ / BM, NTHR, SM_TOT>>>(x, be, sparse);
    rescore_decode_kernel<<<B_, 128>>>(x, We, be, bd, sparse, recon);
}